// round 14
// baseline (speedup 1.0000x reference)
#include <cuda_runtime.h>
#include <cuda_fp16.h>

// GRU autoencoder, SEQ_LEN=4096. fp16 weights, fp32 math.
// R12 (resend of R11): streamed weight rows in REGISTERS (96 half2/warp),
// e2/d1 weights SMEM-resident, contention-free flag barrier, strict
// streamer/chewer warp separation, fully static work assignment.

#define TT    4096
#define H1    2048
#define H2    1024
#define NTHR  512
#define EW    14

__device__ float g_h1[2][H1];
__device__ float g_h2[2][H2];
__device__ float g_hd1[2][H2];
__device__ float g_xgd1[3 * H2];
__device__ float g_ys3[TT][H1];

__device__ unsigned g_flags[256];
__device__ unsigned g_gen;

__device__ __forceinline__ float warp_red(float v) {
    v += __shfl_down_sync(0xffffffffu, v, 16);
    v += __shfl_down_sync(0xffffffffu, v, 8);
    v += __shfl_down_sync(0xffffffffu, v, 4);
    v += __shfl_down_sync(0xffffffffu, v, 2);
    v += __shfl_down_sync(0xffffffffu, v, 1);
    return v;
}

// Contention-free grid barrier: each block STGs its own flag slot; block 0's
// warp 0 scans all slots in parallel, then publishes g_gen. Generation-
// relative, safe across CUDA-graph replays.
__device__ __forceinline__ void flagsync(int nblk, unsigned target) {
    __threadfence();
    __syncthreads();
    if (blockIdx.x == 0) {
        if (threadIdx.x == 0)
            *(volatile unsigned*)&g_flags[0] = target;
        if (threadIdx.x < 32) {
            for (int s = threadIdx.x; s < nblk; s += 32)
                while (*(volatile unsigned*)&g_flags[s] != target) { }
        }
        __syncthreads();
        if (threadIdx.x == 0) {
            __threadfence();
            *(volatile unsigned*)&g_gen = target;
        }
    } else {
        if (threadIdx.x == 0) {
            *(volatile unsigned*)&g_flags[blockIdx.x] = target;
            while (*(volatile unsigned*)&g_gen != target) { }
            __threadfence();
        }
    }
    __syncthreads();
}

__device__ __forceinline__ void acc4(float& a, unsigned lo, unsigned hi, const float4& v) {
    float2 f;
    f = __half22float2(*reinterpret_cast<const __half2*>(&lo));
    a = fmaf(f.x, v.x, a); a = fmaf(f.y, v.y, a);
    f = __half22float2(*reinterpret_cast<const __half2*>(&hi));
    a = fmaf(f.x, v.z, a); a = fmaf(f.y, v.w, a);
}

// 3 gate-dots, fp16 weights in SMEM vs fp32 state in SMEM.
// Per 256-chunk a lane covers [lane*4..+3] and [+128..+131]; state float4
// loads are lane-contiguous (conflict-free).
template <int L>
__device__ __forceinline__ void dot3s(const __half* __restrict__ w0,
                                      const __half* __restrict__ w1,
                                      const __half* __restrict__ w2,
                                      const float* __restrict__ sv,
                                      int lane, float& d0, float& d1, float& d2) {
    float a0 = 0.f, a1 = 0.f, a2 = 0.f;
#pragma unroll 4
    for (int j = 0; j < L / 256; ++j) {
        const int i0 = j * 256 + lane * 4;
        const int i1 = i0 + 128;
        const float4 vA = *reinterpret_cast<const float4*>(sv + i0);
        const float4 vB = *reinterpret_cast<const float4*>(sv + i1);
        uint2 u;
        u = *reinterpret_cast<const uint2*>(w0 + i0); acc4(a0, u.x, u.y, vA);
        u = *reinterpret_cast<const uint2*>(w0 + i1); acc4(a0, u.x, u.y, vB);
        u = *reinterpret_cast<const uint2*>(w1 + i0); acc4(a1, u.x, u.y, vA);
        u = *reinterpret_cast<const uint2*>(w1 + i1); acc4(a1, u.x, u.y, vB);
        u = *reinterpret_cast<const uint2*>(w2 + i0); acc4(a2, u.x, u.y, vA);
        u = *reinterpret_cast<const uint2*>(w2 + i1); acc4(a2, u.x, u.y, vB);
    }
    d0 = warp_red(a0);
    d1 = warp_red(a1);
    d2 = warp_red(a2);
}

// 3 dots of length 2048 with REGISTER-resident fp16 weights (96 half2).
// wr layout: j*12 + gate*4 + {0,1: i0 pair | 2,3: i1 pair}.
__device__ __forceinline__ void dotreg(const __half2* __restrict__ wr,
                                       const float* __restrict__ sv,
                                       int lane, float& d0, float& d1, float& d2) {
    float a0 = 0.f, a1 = 0.f, a2 = 0.f;
#pragma unroll
    for (int j = 0; j < 8; ++j) {
        const int i0 = j * 256 + lane * 4;
        const float4 vA = *reinterpret_cast<const float4*>(sv + i0);
        const float4 vB = *reinterpret_cast<const float4*>(sv + i0 + 128);
        const __half2* w = wr + j * 12;
        float2 f;
        f = __half22float2(w[0]);  a0 = fmaf(f.x, vA.x, a0); a0 = fmaf(f.y, vA.y, a0);
        f = __half22float2(w[1]);  a0 = fmaf(f.x, vA.z, a0); a0 = fmaf(f.y, vA.w, a0);
        f = __half22float2(w[2]);  a0 = fmaf(f.x, vB.x, a0); a0 = fmaf(f.y, vB.y, a0);
        f = __half22float2(w[3]);  a0 = fmaf(f.x, vB.z, a0); a0 = fmaf(f.y, vB.w, a0);
        f = __half22float2(w[4]);  a1 = fmaf(f.x, vA.x, a1); a1 = fmaf(f.y, vA.y, a1);
        f = __half22float2(w[5]);  a1 = fmaf(f.x, vA.z, a1); a1 = fmaf(f.y, vA.w, a1);
        f = __half22float2(w[6]);  a1 = fmaf(f.x, vB.x, a1); a1 = fmaf(f.y, vB.y, a1);
        f = __half22float2(w[7]);  a1 = fmaf(f.x, vB.z, a1); a1 = fmaf(f.y, vB.w, a1);
        f = __half22float2(w[8]);  a2 = fmaf(f.x, vA.x, a2); a2 = fmaf(f.y, vA.y, a2);
        f = __half22float2(w[9]);  a2 = fmaf(f.x, vA.z, a2); a2 = fmaf(f.y, vA.w, a2);
        f = __half22float2(w[10]); a2 = fmaf(f.x, vB.x, a2); a2 = fmaf(f.y, vB.y, a2);
        f = __half22float2(w[11]); a2 = fmaf(f.x, vB.z, a2); a2 = fmaf(f.y, vB.w, a2);
    }
    d0 = warp_red(a0);
    d1 = warp_red(a1);
    d2 = warp_red(a2);
}

// Preload one 3x2048 fp32 gate-row triple into 96 half2 registers.
__device__ __forceinline__ void preload_row(const float* __restrict__ W, int row,
                                            int lane, __half2* __restrict__ wr) {
#pragma unroll
    for (int j = 0; j < 8; ++j) {
#pragma unroll
        for (int g = 0; g < 3; ++g) {
            const float* src = W + (size_t)(row + g * H1) * H1 + j * 256 + lane * 4;
            const float4 a = __ldg(reinterpret_cast<const float4*>(src));
            const float4 b = __ldg(reinterpret_cast<const float4*>(src + 128));
            wr[j * 12 + g * 4 + 0] = __floats2half2_rn(a.x, a.y);
            wr[j * 12 + g * 4 + 1] = __floats2half2_rn(a.z, a.w);
            wr[j * 12 + g * 4 + 2] = __floats2half2_rn(b.x, b.y);
            wr[j * 12 + g * 4 + 3] = __floats2half2_rn(b.z, b.w);
        }
    }
}

__device__ __forceinline__ float sigf(float v) { return 1.f / (1.f + expf(-v)); }

// ---------------- encoder -----------------------------------------------------
__global__ void __launch_bounds__(NTHR, 1) gru_encoder(
    const float* __restrict__ x,
    const float* __restrict__ w1ih, const float* __restrict__ w1hh,
    const float* __restrict__ b1ih, const float* __restrict__ b1hh,
    const float* __restrict__ w2ih, const float* __restrict__ w2hh,
    const float* __restrict__ b2ih, const float* __restrict__ b2hh,
    int nblk)
{
    extern __shared__ __align__(16) float smem[];
    float* s_h1 = smem;                 // h1(t-1)
    float* s_h2 = smem + H1;            // h2(t-2)
    __half* s_w = reinterpret_cast<__half*>(smem + H1 + H2);

    const int tid  = threadIdx.x;
    const int lane = tid & 31;
    const int wid  = tid >> 5;

    const unsigned gb = *(volatile unsigned*)&g_gen;

    const int rlo = blockIdx.x * H2 / nblk;
    const int rhi = (blockIdx.x + 1) * H2 / nblk;
    const int nr  = rhi - rlo;

    // SMEM preload: this block's e2 rows (fp32 -> fp16).
    // Row layout (9216 halfs): ih_r(2048) ih_z ih_n | hh_r(1024) hh_z hh_n.
    for (int idx = tid; idx < nr * 9216; idx += NTHR) {
        const int r = idx / 9216;
        const int p = idx - r * 9216;
        const int i = rlo + r;
        float v;
        if (p < 6144) {
            const int g = p >> 11, c = p & 2047;
            v = __ldg(w2ih + (size_t)(i + g * H2) * H1 + c);
        } else {
            const int q = p - 6144;
            const int g = q >> 10, c = q & 1023;
            v = __ldg(w2hh + (size_t)(i + g * H2) * H2 + c);
        }
        s_w[idx] = __float2half_rn(v);
    }

    // Register preload: one e1 row per streamer warp.
    const int srow = blockIdx.x * EW + wid;
    __half2 wr[96];
    if (wid < EW && srow < H1)
        preload_row(w1hh, srow, lane, wr);
    __syncthreads();

    // e2 rows statically halved between warps EW and EW+1.
    const int halfn = (nr + 1) >> 1;
    const int er0 = (wid == EW) ? 0 : halfn;
    const int er1 = (wid == EW) ? halfn : nr;

    // Iter t: e1 computes h1(t) (t<TT); e2 computes h2(t-1) (t>=1).
    for (int t = 0; t <= TT; ++t) {
        const float* h1p = g_h1[(t + 1) & 1];         // parity of (t-1)
        for (int i = tid * 4; i < H1; i += NTHR * 4) {
            float4 v = (t == 0) ? make_float4(0.f, 0.f, 0.f, 0.f)
                                : __ldcg(reinterpret_cast<const float4*>(h1p + i));
            *reinterpret_cast<float4*>(s_h1 + i) = v;
        }
        const float* h2p = g_h2[t & 1];               // parity of (t-2)
        for (int i = tid * 4; i < H2; i += NTHR * 4) {
            float4 v = (t <= 1) ? make_float4(0.f, 0.f, 0.f, 0.f)
                                : __ldcg(reinterpret_cast<const float4*>(h2p + i));
            *reinterpret_cast<float4*>(s_h2 + i) = v;
        }
        __syncthreads();

        if (wid < EW) {
            if (srow < H1 && t < TT) {                // e1 row, registers
                const int i = srow;
                const float xt = __ldg(x + t);
                float hr, hz, hn;
                dotreg(wr, s_h1, lane, hr, hz, hn);
                if (lane == 0) {
                    const float xr = fmaf(xt, __ldg(w1ih + i),          __ldg(b1ih + i));
                    const float xz = fmaf(xt, __ldg(w1ih + i + H1),     __ldg(b1ih + i + H1));
                    const float xn = fmaf(xt, __ldg(w1ih + i + 2 * H1), __ldg(b1ih + i + 2 * H1));
                    const float r = sigf(xr + hr + __ldg(b1hh + i));
                    const float z = sigf(xz + hz + __ldg(b1hh + i + H1));
                    const float n = tanhf(xn + r * (hn + __ldg(b1hh + i + 2 * H1)));
                    g_h1[t & 1][i] = (1.f - z) * n + z * s_h1[i];
                }
            }
        } else if (t >= 1) {
            for (int r = er0; r < er1; ++r) {         // e2 rows, SMEM: h2(t-1)
                const int i = rlo + r;
                const __half* base = s_w + (size_t)r * 9216;
                float xr, xz, xn, hr, hz, hn;
                dot3s<H1>(base, base + 2048, base + 4096, s_h1, lane, xr, xz, xn);
                dot3s<H2>(base + 6144, base + 7168, base + 8192, s_h2, lane, hr, hz, hn);
                if (lane == 0) {
                    xr += __ldg(b2ih + i);
                    xz += __ldg(b2ih + i + H2);
                    xn += __ldg(b2ih + i + 2 * H2);
                    hr += __ldg(b2hh + i);
                    hz += __ldg(b2hh + i + H2);
                    hn += __ldg(b2hh + i + 2 * H2);
                    const float rr = sigf(xr + hr);
                    const float zz = sigf(xz + hz);
                    const float nn = tanhf(xn + rr * hn);
                    g_h2[(t + 1) & 1][i] = (1.f - zz) * nn + zz * s_h2[i];
                }
            }
        }
        flagsync(nblk, gb + (unsigned)t + 1u);
    }
}

// ---------------- d1 constant input-gate preactivation ------------------------
// emb = final h2 = h2(TT-1), stored at parity (TT-1)&1 == 1.
__global__ void gru_xgd1(const float* __restrict__ d1ih,
                         const float* __restrict__ d1bih)
{
    const int lane = threadIdx.x & 31;
    const int gw = blockIdx.x * (blockDim.x >> 5) + (threadIdx.x >> 5);
    const int nw = gridDim.x * (blockDim.x >> 5);
    for (int j = gw; j < 3 * H2; j += nw) {
        float a = 0.f;
        const float* w = d1ih + (size_t)j * H2;
#pragma unroll 4
        for (int q = 0; q < H2 / 128; ++q) {
            const int idx = q * 128 + lane * 4;
            const float4 r = __ldg(reinterpret_cast<const float4*>(w + idx));
            const float4 v = __ldcg(reinterpret_cast<const float4*>(&g_h2[1][idx]));
            a = fmaf(r.x, v.x, a); a = fmaf(r.y, v.y, a);
            a = fmaf(r.z, v.z, a); a = fmaf(r.w, v.w, a);
        }
        a = warp_red(a);
        if (lane == 0) g_xgd1[j] = a + __ldg(d1bih + j);
    }
}

// ---------------- decoder -----------------------------------------------------
__global__ void __launch_bounds__(NTHR, 1) gru_decoder(
    const float* __restrict__ b1hh,
    const float* __restrict__ d2ih, const float* __restrict__ d2hh,
    const float* __restrict__ b2ih, const float* __restrict__ b2hh,
    const float* __restrict__ d1hh,
    int nblk)
{
    extern __shared__ __align__(16) float smem[];
    float* s_d1 = smem;                 // hd1(t-1) == ys2(t-1)
    float* s_y3 = smem + H2;            // ys3(t-2)
    __half* s_w = reinterpret_cast<__half*>(smem + H1 + H2);

    const int tid  = threadIdx.x;
    const int lane = tid & 31;
    const int wid  = tid >> 5;

    const unsigned gb = *(volatile unsigned*)&g_gen;

    const int d1lo = blockIdx.x * H2 / nblk;
    const int d1hi = (blockIdx.x + 1) * H2 / nblk;
    const int nd1  = d1hi - d1lo;

    // SMEM preload: d2-ih slabs for the EW streamed rows (3072 halfs each:
    // ih_r(1024) ih_z ih_n), then this block's d1 rows (hh_r hh_z hh_n).
    const int totalH = EW * 3072 + nd1 * 3072;
    for (int idx = tid; idx < totalH; idx += NTHR) {
        float v = 0.f;
        if (idx < EW * 3072) {
            const int r = idx / 3072;
            const int p = idx - r * 3072;
            const int i = blockIdx.x * EW + r;
            if (i < H1) {
                const int g = p >> 10, c = p & 1023;
                v = __ldg(d2ih + (size_t)(i + g * H1) * H2 + c);
            }
        } else {
            const int idx2 = idx - EW * 3072;
            const int r = idx2 / 3072;
            const int p = idx2 - r * 3072;
            const int i = d1lo + r;
            const int g = p >> 10, c = p & 1023;
            v = __ldg(d1hh + (size_t)(i + g * H2) * H2 + c);
        }
        s_w[idx] = __float2half_rn(v);
    }

    // Register preload: one d2 hh-row per streamer warp.
    const int srow = blockIdx.x * EW + wid;
    __half2 wr[96];
    if (wid < EW && srow < H1)
        preload_row(d2hh, srow, lane, wr);
    __syncthreads();

    const int halfn = (nd1 + 1) >> 1;
    const int dr0 = (wid == EW) ? 0 : halfn;
    const int dr1 = (wid == EW) ? halfn : nd1;

    for (int t = 0; t <= TT; ++t) {
        const int s = t - 1;                          // d2 computes ys3[s]
        const float* d1p = g_hd1[(t + 1) & 1];
        for (int i = tid * 4; i < H2; i += NTHR * 4) {
            float4 v = (t == 0) ? make_float4(0.f, 0.f, 0.f, 0.f)
                                : __ldcg(reinterpret_cast<const float4*>(d1p + i));
            *reinterpret_cast<float4*>(s_d1 + i) = v;
        }
        for (int i = tid * 4; i < H1; i += NTHR * 4) {
            float4 v = (t <= 1) ? make_float4(0.f, 0.f, 0.f, 0.f)
                                : __ldcg(reinterpret_cast<const float4*>(&g_ys3[s - 1][i]));
            *reinterpret_cast<float4*>(s_y3 + i) = v;
        }
        __syncthreads();

        if (wid < EW) {
            if (srow < H1 && t >= 1) {                // d2 row: ys3[s]
                const int i = srow;
                const __half* base = s_w + (size_t)wid * 3072;
                float xr, xz, xn, hr, hz, hn;
                dot3s<H2>(base, base + 1024, base + 2048, s_d1, lane, xr, xz, xn);
                dotreg(wr, s_y3, lane, hr, hz, hn);
                if (lane == 0) {
                    xr += __ldg(b2ih + i);
                    xz += __ldg(b2ih + i + H1);
                    xn += __ldg(b2ih + i + 2 * H1);
                    hr += __ldg(b2hh + i);
                    hz += __ldg(b2hh + i + H1);
                    hn += __ldg(b2hh + i + 2 * H1);
                    const float r = sigf(xr + hr);
                    const float z = sigf(xz + hz);
                    const float n = tanhf(xn + r * hn);
                    g_ys3[s][i] = (1.f - z) * n + z * s_y3[i];
                }
            }
        } else if (t < TT) {
            for (int r = dr0; r < dr1; ++r) {         // d1 rows: hd1(t)
                const int i = d1lo + r;
                const __half* base = s_w + (size_t)(EW + r) * 3072;
                float hr, hz, hn;
                dot3s<H2>(base, base + 1024, base + 2048, s_d1, lane, hr, hz, hn);
                if (lane == 0) {
                    const float xr = g_xgd1[i];       // includes bih
                    const float xz = g_xgd1[i + H2];
                    const float xn = g_xgd1[i + 2 * H2];
                    const float hrb = hr + __ldg(b1hh + i);
                    const float hzb = hz + __ldg(b1hh + i + H2);
                    const float hnb = hn + __ldg(b1hh + i + 2 * H2);
                    const float rr = sigf(xr + hrb);
                    const float zz = sigf(xz + hzb);
                    const float nn = tanhf(xn + rr * hnb);
                    g_hd1[t & 1][i] = (1.f - zz) * nn + zz * s_d1[i];
                }
            }
        }
        flagsync(nblk, gb + (unsigned)t + 1u);
    }
}

// ---------------- output head: out[t] = ys3[t] . out_W + out_b ----------------
__global__ void gru_output(const float* __restrict__ ow,
                           const float* __restrict__ ob,
                           float* __restrict__ out)
{
    const int lane = threadIdx.x & 31;
    const int gw = blockIdx.x * (blockDim.x >> 5) + (threadIdx.x >> 5);
    const int nw = gridDim.x * (blockDim.x >> 5);
    for (int t = gw; t < TT; t += nw) {
        float a = 0.f;
#pragma unroll 4
        for (int q = 0; q < H1 / 128; ++q) {
            const int idx = q * 128 + lane * 4;
            const float4 w = __ldg(reinterpret_cast<const float4*>(ow + idx));
            const float4 v = *reinterpret_cast<const float4*>(&g_ys3[t][idx]);
            a = fmaf(w.x, v.x, a); a = fmaf(w.y, v.y, a);
            a = fmaf(w.z, v.z, a); a = fmaf(w.w, v.w, a);
        }
        a = warp_red(a);
        if (lane == 0) out[t] = a + __ldg(ob);
    }
}

// ---------------- launch ------------------------------------------------------
extern "C" void kernel_launch(void* const* d_in, const int* in_sizes, int n_in,
                              void* d_out, int out_size) {
    const float* x      = (const float*)d_in[0];
    const float* e1_Wih = (const float*)d_in[1];
    const float* e1_Whh = (const float*)d_in[2];
    const float* e1_bih = (const float*)d_in[3];
    const float* e1_bhh = (const float*)d_in[4];
    const float* e2_Wih = (const float*)d_in[5];
    const float* e2_Whh = (const float*)d_in[6];
    const float* e2_bih = (const float*)d_in[7];
    const float* e2_bhh = (const float*)d_in[8];
    const float* d1_Wih = (const float*)d_in[9];
    const float* d1_Whh = (const float*)d_in[10];
    const float* d1_bih = (const float*)d_in[11];
    const float* d1_bhh = (const float*)d_in[12];
    const float* d2_Wih = (const float*)d_in[13];
    const float* d2_Whh = (const float*)d_in[14];
    const float* d2_bih = (const float*)d_in[15];
    const float* d2_bhh = (const float*)d_in[16];
    const float* out_W  = (const float*)d_in[17];
    const float* out_b  = (const float*)d_in[18];

    int nblk = 148;
    cudaDeviceGetAttribute(&nblk, cudaDevAttrMultiProcessorCount, 0);

    const int nrMax = (H2 + nblk - 1) / nblk;
    const int smemE = (H1 + H2) * 4 + nrMax * 9216 * 2;
    const int smemD = (H1 + H2) * 4 + (EW + nrMax) * 3072 * 2;

    cudaFuncSetAttribute(gru_encoder, cudaFuncAttributeMaxDynamicSharedMemorySize, smemE);
    cudaFuncSetAttribute(gru_decoder, cudaFuncAttributeMaxDynamicSharedMemorySize, smemD);

    gru_encoder<<<nblk, NTHR, smemE>>>(x, e1_Wih, e1_Whh, e1_bih, e1_bhh,
                                       e2_Wih, e2_Whh, e2_bih, e2_bhh, nblk);
    gru_xgd1<<<96, 256>>>(d1_Wih, d1_bih);
    gru_decoder<<<nblk, NTHR, smemD>>>(d1_bhh, d2_Wih, d2_Whh, d2_bih, d2_bhh,
                                       d1_Whh, nblk);
    gru_output<<<256, 256>>>(out_W, out_b, (float*)d_out);
}

// round 15
// speedup vs baseline: 1.0676x; 1.0676x over previous
#include <cuda_runtime.h>
#include <cuda_fp16.h>

// GRU autoencoder, SEQ_LEN=4096, fp16-compressed streamed weights, fp32 math.
// R15 = R5 base (512 thr, unroll-4 dot3h, fp16 weights streamed from L2)
//       + slot-based static partition (max 4 weight-units per warp, vs 6)
//       + contention-free flag grid barrier (no 148-way atomic).
// e1: 1 -> 2048, e2: 2048 -> 1024 (pipelined, 1 grid-sync/step)
// d1: 1024 -> 1024 (constant input => xg precomputed), d2: 1024 -> 2048
// head: 2048 -> 1

#define TT    4096
#define H1    2048     // e1 / d2 hidden
#define H2    1024     // e2 / d1 hidden
#define NTHR  512
#define WPB   (NTHR >> 5)

// ---------------- device scratch ----------------------------------------------
__device__ float g_h1[2][H1];        // e1 state, double buffered by time parity
__device__ float g_h2[2][H2];        // e2 state
__device__ float g_hd1[2][H2];       // d1 state
__device__ float g_xgd1[3 * H2];     // constant input-gate preactivation for d1
__device__ float g_ys3[TT][H1];      // d2 outputs (also d2 state history)

// fp16 copies of the streamed weight matrices (converted on every launch)
__device__ __align__(16) __half c_w1hh[3 * H1 * H1];
__device__ __align__(16) __half c_w2ih[3 * H2 * H1];
__device__ __align__(16) __half c_w2hh[3 * H2 * H2];
__device__ __align__(16) __half c_d1hh[3 * H2 * H2];
__device__ __align__(16) __half c_d2ih[3 * H1 * H2];
__device__ __align__(16) __half c_d2hh[3 * H1 * H1];

__device__ unsigned g_flags[256];    // per-block arrival flags (zero at load)
__device__ unsigned g_gen;           // release generation   (zero at load)

// ---------------- helpers -----------------------------------------------------
__device__ __forceinline__ float warp_red(float v) {
    v += __shfl_down_sync(0xffffffffu, v, 16);
    v += __shfl_down_sync(0xffffffffu, v, 8);
    v += __shfl_down_sync(0xffffffffu, v, 4);
    v += __shfl_down_sync(0xffffffffu, v, 2);
    v += __shfl_down_sync(0xffffffffu, v, 1);
    return v;
}

// Contention-free grid barrier: each block STGs its own flag slot; block 0's
// warp 0 scans all slots in parallel, then publishes g_gen. Generation-
// relative, safe across CUDA-graph replays (verified in R14).
__device__ __forceinline__ void flagsync(int nblk, unsigned target) {
    __threadfence();
    __syncthreads();
    if (blockIdx.x == 0) {
        if (threadIdx.x == 0)
            *(volatile unsigned*)&g_flags[0] = target;
        if (threadIdx.x < 32) {
            for (int s = threadIdx.x; s < nblk; s += 32)
                while (*(volatile unsigned*)&g_flags[s] != target) { }
        }
        __syncthreads();
        if (threadIdx.x == 0) {
            __threadfence();
            *(volatile unsigned*)&g_gen = target;
        }
    } else {
        if (threadIdx.x == 0) {
            *(volatile unsigned*)&g_flags[blockIdx.x] = target;
            while (*(volatile unsigned*)&g_gen != target) { }
            __threadfence();
        }
    }
    __syncthreads();
}

__device__ __forceinline__ void acc8(float& a, const uint4& r,
                                     const float4& vA, const float4& vB) {
    float2 f;
    f = __half22float2(*reinterpret_cast<const __half2*>(&r.x));
    a = fmaf(f.x, vA.x, a); a = fmaf(f.y, vA.y, a);
    f = __half22float2(*reinterpret_cast<const __half2*>(&r.y));
    a = fmaf(f.x, vA.z, a); a = fmaf(f.y, vA.w, a);
    f = __half22float2(*reinterpret_cast<const __half2*>(&r.z));
    a = fmaf(f.x, vB.x, a); a = fmaf(f.y, vB.y, a);
    f = __half22float2(*reinterpret_cast<const __half2*>(&r.w));
    a = fmaf(f.x, vB.z, a); a = fmaf(f.y, vB.w, a);
}

// 3 simultaneous gate dots (fp16 global weights vs fp32 SMEM vector).
// Unroll 4 => up to 12 LDG.128 batched per warp to cover L2 latency.
template <int L>
__device__ __forceinline__ void dot3h(const __half* __restrict__ w0,
                                      const __half* __restrict__ w1,
                                      const __half* __restrict__ w2,
                                      const float* __restrict__ sv,
                                      int lane, float& d0, float& d1, float& d2) {
    float a0 = 0.f, a1 = 0.f, a2 = 0.f;
#pragma unroll 4
    for (int j = 0; j < L / 256; ++j) {
        const int idx = j * 256 + lane * 8;
        const uint4 r0 = __ldg(reinterpret_cast<const uint4*>(w0 + idx));
        const uint4 r1 = __ldg(reinterpret_cast<const uint4*>(w1 + idx));
        const uint4 r2 = __ldg(reinterpret_cast<const uint4*>(w2 + idx));
        const float4 vA = *reinterpret_cast<const float4*>(sv + idx);
        const float4 vB = *reinterpret_cast<const float4*>(sv + idx + 4);
        acc8(a0, r0, vA, vB);
        acc8(a1, r1, vA, vB);
        acc8(a2, r2, vA, vB);
    }
    d0 = warp_red(a0);
    d1 = warp_red(a1);
    d2 = warp_red(a2);
}

__device__ __forceinline__ float sigf(float v) { return 1.f / (1.f + expf(-v)); }

// ---------------- fp32 -> fp16 weight conversion ------------------------------
__global__ void f2h_kernel(const float* __restrict__ src, __half* __restrict__ dst, int n) {
    const int stride = gridDim.x * blockDim.x * 8;
    for (int i = (blockIdx.x * blockDim.x + threadIdx.x) * 8; i < n; i += stride) {
        const float4 a = __ldg(reinterpret_cast<const float4*>(src + i));
        const float4 b = __ldg(reinterpret_cast<const float4*>(src + i + 4));
        const __half2 h0 = __floats2half2_rn(a.x, a.y);
        const __half2 h1 = __floats2half2_rn(a.z, a.w);
        const __half2 h2 = __floats2half2_rn(b.x, b.y);
        const __half2 h3 = __floats2half2_rn(b.z, b.w);
        uint4 o;
        o.x = *reinterpret_cast<const unsigned int*>(&h0);
        o.y = *reinterpret_cast<const unsigned int*>(&h1);
        o.z = *reinterpret_cast<const unsigned int*>(&h2);
        o.w = *reinterpret_cast<const unsigned int*>(&h3);
        *reinterpret_cast<uint4*>(dst + i) = o;
    }
}

// ---------------- encoder: e1 (1->2048) + e2 (2048->1024), pipelined ----------
// Slot partition: warps 0..1023 -> one e2 row (3 units).
//                 warps 1024..NW-1 -> 2048 e1 rows split evenly (2 or 4 units).
__global__ void __launch_bounds__(NTHR, 1) gru_encoder(
    const float* __restrict__ x,
    const float* __restrict__ w1ih, const float* __restrict__ b1ih,
    const float* __restrict__ b1hh,
    const float* __restrict__ b2ih, const float* __restrict__ b2hh,
    int nblk)
{
    __shared__ __align__(16) float s_h1[H1];   // h1(t-1) == ys1(t-1)
    __shared__ __align__(16) float s_h2[H2];   // h2(t-2)
    const int tid  = threadIdx.x;
    const int lane = tid & 31;
    const int gw   = blockIdx.x * WPB + (tid >> 5);
    const int NW   = nblk * WPB;

    const unsigned gb = *(volatile unsigned*)&g_gen;

    const bool isE2 = (gw < H2);
    const int e2row = gw;
    const int nE1W  = NW - H2;                 // warps available for e1
    const int e1idx = gw - H2;
    int e1lo = 0, e1hi = 0;
    if (!isE2) {
        e1lo = (int)((long long)e1idx * H1 / nE1W);
        e1hi = (int)((long long)(e1idx + 1) * H1 / nE1W);
    }

    // Iter t: e1 computes h1(t) (t<TT); e2 computes h2(t-1) (t>=1).
    for (int t = 0; t <= TT; ++t) {
        const float* h1p = g_h1[(t + 1) & 1];   // parity of (t-1)
        for (int i = tid * 4; i < H1; i += NTHR * 4) {
            float4 v = (t == 0) ? make_float4(0.f, 0.f, 0.f, 0.f)
                                : __ldcg(reinterpret_cast<const float4*>(h1p + i));
            *reinterpret_cast<float4*>(s_h1 + i) = v;
        }
        const float* h2p = g_h2[t & 1];          // parity of (t-2)
        for (int i = tid * 4; i < H2; i += NTHR * 4) {
            float4 v = (t <= 1) ? make_float4(0.f, 0.f, 0.f, 0.f)
                                : __ldcg(reinterpret_cast<const float4*>(h2p + i));
            *reinterpret_cast<float4*>(s_h2 + i) = v;
        }
        __syncthreads();

        if (isE2) {
            if (t >= 1) {                        // computing h2(t-1)
                const int i = e2row;
                float xr, xz, xn, hr, hz, hn;
                dot3h<H1>(c_w2ih + (size_t)i * H1,
                          c_w2ih + (size_t)(i + H2) * H1,
                          c_w2ih + (size_t)(i + 2 * H2) * H1,
                          s_h1, lane, xr, xz, xn);             // input = ys1(t-1)
                dot3h<H2>(c_w2hh + (size_t)i * H2,
                          c_w2hh + (size_t)(i + H2) * H2,
                          c_w2hh + (size_t)(i + 2 * H2) * H2,
                          s_h2, lane, hr, hz, hn);
                if (lane == 0) {
                    xr += __ldg(b2ih + i);
                    xz += __ldg(b2ih + i + H2);
                    xn += __ldg(b2ih + i + 2 * H2);
                    hr += __ldg(b2hh + i);
                    hz += __ldg(b2hh + i + H2);
                    hn += __ldg(b2hh + i + 2 * H2);
                    const float r = sigf(xr + hr);
                    const float z = sigf(xz + hz);
                    const float n = tanhf(xn + r * hn);
                    g_h2[(t + 1) & 1][i] = (1.f - z) * n + z * s_h2[i];
                }
            }
        } else if (t < TT) {
            const float xt = __ldg(x + t);
            for (int i = e1lo; i < e1hi; ++i) {
                float hr, hz, hn;
                dot3h<H1>(c_w1hh + (size_t)i * H1,
                          c_w1hh + (size_t)(i + H1) * H1,
                          c_w1hh + (size_t)(i + 2 * H1) * H1,
                          s_h1, lane, hr, hz, hn);
                if (lane == 0) {
                    const float xr = fmaf(xt, __ldg(w1ih + i),          __ldg(b1ih + i));
                    const float xz = fmaf(xt, __ldg(w1ih + i + H1),     __ldg(b1ih + i + H1));
                    const float xn = fmaf(xt, __ldg(w1ih + i + 2 * H1), __ldg(b1ih + i + 2 * H1));
                    hr += __ldg(b1hh + i);
                    hz += __ldg(b1hh + i + H1);
                    hn += __ldg(b1hh + i + 2 * H1);
                    const float r = sigf(xr + hr);
                    const float z = sigf(xz + hz);
                    const float n = tanhf(xn + r * hn);
                    g_h1[t & 1][i] = (1.f - z) * n + z * s_h1[i];
                }
            }
        }
        flagsync(nblk, gb + (unsigned)t + 1u);
    }
}

// ---------------- d1 constant input-gate preactivation ------------------------
// emb = final h2 = h2(TT-1), stored at parity (TT-1)&1 == 1.
__global__ void gru_xgd1(const float* __restrict__ d1ih,
                         const float* __restrict__ d1bih)
{
    const int lane = threadIdx.x & 31;
    const int gw = blockIdx.x * (blockDim.x >> 5) + (threadIdx.x >> 5);
    const int nw = gridDim.x * (blockDim.x >> 5);
    for (int j = gw; j < 3 * H2; j += nw) {
        float a = 0.f;
        const float* w = d1ih + (size_t)j * H2;
#pragma unroll 4
        for (int q = 0; q < H2 / 128; ++q) {
            const int idx = q * 128 + lane * 4;
            const float4 r = __ldg(reinterpret_cast<const float4*>(w + idx));
            const float4 v = __ldcg(reinterpret_cast<const float4*>(&g_h2[1][idx]));
            a = fmaf(r.x, v.x, a); a = fmaf(r.y, v.y, a);
            a = fmaf(r.z, v.z, a); a = fmaf(r.w, v.w, a);
        }
        a = warp_red(a);
        if (lane == 0) g_xgd1[j] = a + __ldg(d1bih + j);
    }
}

// ---------------- decoder: d1 (const in ->1024) + d2 (1024->2048), pipelined --
// Slot partition: warps 0..2047 -> one d2 row (3 units).
//                 warps 2048..NW-1 -> 1024 d1 rows split evenly (~3 units).
__global__ void __launch_bounds__(NTHR, 1) gru_decoder(
    const float* __restrict__ b1hh,
    const float* __restrict__ b2ih, const float* __restrict__ b2hh,
    int nblk)
{
    __shared__ __align__(16) float s_d1[H2];   // hd1(t-1) == ys2(t-1)
    __shared__ __align__(16) float s_y3[H1];   // ys3(t-2) == hd2 prev state
    const int tid  = threadIdx.x;
    const int lane = tid & 31;
    const int gw   = blockIdx.x * WPB + (tid >> 5);
    const int NW   = nblk * WPB;

    const unsigned gb = *(volatile unsigned*)&g_gen;

    const bool isD2 = (gw < H1);
    const int d2row = gw;
    const int nD1W  = NW - H1;                 // warps available for d1
    const int d1idx = gw - H1;
    int d1lo = 0, d1hi = 0;
    if (!isD2) {
        d1lo = (int)((long long)d1idx * H2 / nD1W);
        d1hi = (int)((long long)(d1idx + 1) * H2 / nD1W);
    }

    for (int t = 0; t <= TT; ++t) {
        const int s = t - 1;                    // d2 computes ys3[s]
        const float* d1p = g_hd1[(t + 1) & 1];
        for (int i = tid * 4; i < H2; i += NTHR * 4) {
            float4 v = (t == 0) ? make_float4(0.f, 0.f, 0.f, 0.f)
                                : __ldcg(reinterpret_cast<const float4*>(d1p + i));
            *reinterpret_cast<float4*>(s_d1 + i) = v;
        }
        for (int i = tid * 4; i < H1; i += NTHR * 4) {
            float4 v = (t <= 1) ? make_float4(0.f, 0.f, 0.f, 0.f)
                                : __ldcg(reinterpret_cast<const float4*>(&g_ys3[s - 1][i]));
            *reinterpret_cast<float4*>(s_y3 + i) = v;
        }
        __syncthreads();

        if (isD2) {
            if (t >= 1) {                        // d2 output, computing ys3[s]
                const int i = d2row;
                float xr, xz, xn, hr, hz, hn;
                dot3h<H2>(c_d2ih + (size_t)i * H2,
                          c_d2ih + (size_t)(i + H1) * H2,
                          c_d2ih + (size_t)(i + 2 * H1) * H2,
                          s_d1, lane, xr, xz, xn);           // input = ys2(s)
                dot3h<H1>(c_d2hh + (size_t)i * H1,
                          c_d2hh + (size_t)(i + H1) * H1,
                          c_d2hh + (size_t)(i + 2 * H1) * H1,
                          s_y3, lane, hr, hz, hn);
                if (lane == 0) {
                    xr += __ldg(b2ih + i);
                    xz += __ldg(b2ih + i + H1);
                    xn += __ldg(b2ih + i + 2 * H1);
                    hr += __ldg(b2hh + i);
                    hz += __ldg(b2hh + i + H1);
                    hn += __ldg(b2hh + i + 2 * H1);
                    const float r = sigf(xr + hr);
                    const float z = sigf(xz + hz);
                    const float n = tanhf(xn + r * hn);
                    g_ys3[s][i] = (1.f - z) * n + z * s_y3[i];
                }
            }
        } else if (t < TT) {
            for (int i = d1lo; i < d1hi; ++i) {  // d1 output, computing hd1(t)
                float hr, hz, hn;
                dot3h<H2>(c_d1hh + (size_t)i * H2,
                          c_d1hh + (size_t)(i + H2) * H2,
                          c_d1hh + (size_t)(i + 2 * H2) * H2,
                          s_d1, lane, hr, hz, hn);
                if (lane == 0) {
                    const float xr = g_xgd1[i];             // includes bih
                    const float xz = g_xgd1[i + H2];
                    const float xn = g_xgd1[i + 2 * H2];
                    hr += __ldg(b1hh + i);
                    hz += __ldg(b1hh + i + H2);
                    hn += __ldg(b1hh + i + 2 * H2);
                    const float r = sigf(xr + hr);
                    const float z = sigf(xz + hz);
                    const float n = tanhf(xn + r * hn);
                    g_hd1[t & 1][i] = (1.f - z) * n + z * s_d1[i];
                }
            }
        }
        flagsync(nblk, gb + (unsigned)t + 1u);
    }
}

// ---------------- output head: out[t] = ys3[t] . out_W + out_b ----------------
__global__ void gru_output(const float* __restrict__ ow,
                           const float* __restrict__ ob,
                           float* __restrict__ out)
{
    const int lane = threadIdx.x & 31;
    const int gw = blockIdx.x * (blockDim.x >> 5) + (threadIdx.x >> 5);
    const int nw = gridDim.x * (blockDim.x >> 5);
    for (int t = gw; t < TT; t += nw) {
        float a = 0.f;
#pragma unroll 4
        for (int q = 0; q < H1 / 128; ++q) {
            const int idx = q * 128 + lane * 4;
            const float4 w = __ldg(reinterpret_cast<const float4*>(ow + idx));
            const float4 v = *reinterpret_cast<const float4*>(&g_ys3[t][idx]);
            a = fmaf(w.x, v.x, a); a = fmaf(w.y, v.y, a);
            a = fmaf(w.z, v.z, a); a = fmaf(w.w, v.w, a);
        }
        a = warp_red(a);
        if (lane == 0) out[t] = a + __ldg(ob);
    }
}

// ---------------- launch ------------------------------------------------------
extern "C" void kernel_launch(void* const* d_in, const int* in_sizes, int n_in,
                              void* d_out, int out_size) {
    const float* x      = (const float*)d_in[0];
    const float* e1_Wih = (const float*)d_in[1];
    const float* e1_Whh = (const float*)d_in[2];
    const float* e1_bih = (const float*)d_in[3];
    const float* e1_bhh = (const float*)d_in[4];
    const float* e2_Wih = (const float*)d_in[5];
    const float* e2_Whh = (const float*)d_in[6];
    const float* e2_bih = (const float*)d_in[7];
    const float* e2_bhh = (const float*)d_in[8];
    const float* d1_Wih = (const float*)d_in[9];
    const float* d1_Whh = (const float*)d_in[10];
    const float* d1_bih = (const float*)d_in[11];
    const float* d1_bhh = (const float*)d_in[12];
    const float* d2_Wih = (const float*)d_in[13];
    const float* d2_Whh = (const float*)d_in[14];
    const float* d2_bih = (const float*)d_in[15];
    const float* d2_bhh = (const float*)d_in[16];
    const float* out_W  = (const float*)d_in[17];
    const float* out_b  = (const float*)d_in[18];

    int nblk = 148;
    cudaDeviceGetAttribute(&nblk, cudaDevAttrMultiProcessorCount, 0);

    __half* p_w1hh; cudaGetSymbolAddress((void**)&p_w1hh, c_w1hh);
    __half* p_w2ih; cudaGetSymbolAddress((void**)&p_w2ih, c_w2ih);
    __half* p_w2hh; cudaGetSymbolAddress((void**)&p_w2hh, c_w2hh);
    __half* p_d1hh; cudaGetSymbolAddress((void**)&p_d1hh, c_d1hh);
    __half* p_d2ih; cudaGetSymbolAddress((void**)&p_d2ih, c_d2ih);
    __half* p_d2hh; cudaGetSymbolAddress((void**)&p_d2hh, c_d2hh);

    f2h_kernel<<<512, 256>>>(e1_Whh, p_w1hh, 3 * H1 * H1);
    f2h_kernel<<<512, 256>>>(e2_Wih, p_w2ih, 3 * H2 * H1);
    f2h_kernel<<<512, 256>>>(e2_Whh, p_w2hh, 3 * H2 * H2);
    f2h_kernel<<<512, 256>>>(d1_Whh, p_d1hh, 3 * H2 * H2);
    f2h_kernel<<<512, 256>>>(d2_Wih, p_d2ih, 3 * H1 * H2);
    f2h_kernel<<<512, 256>>>(d2_Whh, p_d2hh, 3 * H1 * H1);

    gru_encoder<<<nblk, NTHR>>>(x, e1_Wih, e1_bih, e1_bhh, e2_bih, e2_bhh, nblk);
    gru_xgd1<<<96, 256>>>(d1_Wih, d1_bih);
    gru_decoder<<<nblk, NTHR>>>(d1_bhh, d2_bih, d2_bhh, nblk);
    gru_output<<<256, 256>>>(out_W, out_b, (float*)d_out);
}

// round 17
// speedup vs baseline: 1.1023x; 1.0325x over previous
#include <cuda_runtime.h>
#include <cuda_fp16.h>
#include <cuda_pipeline.h>

// GRU autoencoder, SEQ_LEN=4096, fp16-compressed streamed weights, fp32 math.
// R16 = R5 base (512 thr, weighted static partition, atomic grid barrier)
//       with dot products streamed via cp.async DOUBLE-BUFFERED per-warp SMEM
//       staging (loads stay in flight through compute + reduction tails).
// e1: 1 -> 2048, e2: 2048 -> 1024 (pipelined, 1 grid-sync/step)
// d1: 1024 -> 1024 (constant input => xg precomputed), d2: 1024 -> 2048
// head: 2048 -> 1

#define TT    4096
#define H1    2048
#define H2    1024
#define NTHR  512
#define WPB   (NTHR >> 5)

// chunk = 512 halfs per gate (2 j-blocks of 256); 3 gates => 3KB per chunk.
// Per-warp double buffer = 6144 B. 16 warps => 96 KB + 12 KB states.
#define WBUF_BYTES 6144
#define SMEM_TOTAL ((H1 + H2) * 4 + 16 * WBUF_BYTES)

// ---------------- device scratch ----------------------------------------------
__device__ float g_h1[2][H1];
__device__ float g_h2[2][H2];
__device__ float g_hd1[2][H2];
__device__ float g_xgd1[3 * H2];
__device__ float g_ys3[TT][H1];

__device__ __align__(16) __half c_w1hh[3 * H1 * H1];
__device__ __align__(16) __half c_w2ih[3 * H2 * H1];
__device__ __align__(16) __half c_w2hh[3 * H2 * H2];
__device__ __align__(16) __half c_d1hh[3 * H2 * H2];
__device__ __align__(16) __half c_d2ih[3 * H1 * H2];
__device__ __align__(16) __half c_d2hh[3 * H1 * H1];

__device__ __align__(128) unsigned int g_barcnt[32];
__device__ __align__(128) unsigned int g_bargen[32];

// ---------------- helpers -----------------------------------------------------
__device__ __forceinline__ float warp_red(float v) {
    v += __shfl_down_sync(0xffffffffu, v, 16);
    v += __shfl_down_sync(0xffffffffu, v, 8);
    v += __shfl_down_sync(0xffffffffu, v, 4);
    v += __shfl_down_sync(0xffffffffu, v, 2);
    v += __shfl_down_sync(0xffffffffu, v, 1);
    return v;
}

__device__ __forceinline__ void gridsync(int nblk) {
    __threadfence();
    __syncthreads();
    if (threadIdx.x == 0) {
        volatile unsigned int* gen = &g_bargen[0];
        unsigned int g = *gen;
        if (atomicAdd(&g_barcnt[0], 1u) == (unsigned)(nblk - 1)) {
            g_barcnt[0] = 0;
            __threadfence();
            *gen = g + 1;
        } else {
            while (*gen == g) { }
        }
        __threadfence();
    }
    __syncthreads();
}

__device__ __forceinline__ void acc8(float& a, const uint4& r,
                                     const float4& vA, const float4& vB) {
    float2 f;
    f = __half22float2(*reinterpret_cast<const __half2*>(&r.x));
    a = fmaf(f.x, vA.x, a); a = fmaf(f.y, vA.y, a);
    f = __half22float2(*reinterpret_cast<const __half2*>(&r.y));
    a = fmaf(f.x, vA.z, a); a = fmaf(f.y, vA.w, a);
    f = __half22float2(*reinterpret_cast<const __half2*>(&r.z));
    a = fmaf(f.x, vB.x, a); a = fmaf(f.y, vB.y, a);
    f = __half22float2(*reinterpret_cast<const __half2*>(&r.w));
    a = fmaf(f.x, vB.z, a); a = fmaf(f.y, vB.w, a);
}

// Issue one chunk (segment-local index c) of 3 gate rows into buf[par].
// Each lane copies the exact 6x16B it later reads: conflict-free.
__device__ __forceinline__ void issue_chunk(const __half* __restrict__ w0,
                                            const __half* __restrict__ w1,
                                            const __half* __restrict__ w2,
                                            int c, char* buf, int par, int lane) {
    char* dst = buf + par * 3072 + lane * 16;
    const int base = c * 512 + lane * 8;
    __pipeline_memcpy_async(dst,              w0 + base,       16);
    __pipeline_memcpy_async(dst + 512,        w0 + base + 256, 16);
    __pipeline_memcpy_async(dst + 1024,       w1 + base,       16);
    __pipeline_memcpy_async(dst + 1024 + 512, w1 + base + 256, 16);
    __pipeline_memcpy_async(dst + 2048,       w2 + base,       16);
    __pipeline_memcpy_async(dst + 2048 + 512, w2 + base + 256, 16);
    __pipeline_commit();
}

__device__ __forceinline__ void compute_chunk(const float* __restrict__ sv,
                                              int c, const char* buf, int par, int lane,
                                              float& a0, float& a1, float& a2) {
    const char* src = buf + par * 3072 + lane * 16;
    const int vb = c * 512 + lane * 8;
    const float4 vA0 = *reinterpret_cast<const float4*>(sv + vb);
    const float4 vB0 = *reinterpret_cast<const float4*>(sv + vb + 4);
    const float4 vA1 = *reinterpret_cast<const float4*>(sv + vb + 256);
    const float4 vB1 = *reinterpret_cast<const float4*>(sv + vb + 260);
    uint4 r;
    r = *reinterpret_cast<const uint4*>(src);              acc8(a0, r, vA0, vB0);
    r = *reinterpret_cast<const uint4*>(src + 512);        acc8(a0, r, vA1, vB1);
    r = *reinterpret_cast<const uint4*>(src + 1024);       acc8(a1, r, vA0, vB0);
    r = *reinterpret_cast<const uint4*>(src + 1024 + 512); acc8(a1, r, vA1, vB1);
    r = *reinterpret_cast<const uint4*>(src + 2048);       acc8(a2, r, vA0, vB0);
    r = *reinterpret_cast<const uint4*>(src + 2048 + 512); acc8(a2, r, vA1, vB1);
}

// Pipelined dual-segment triple-gate dots. Segment A: NA chunks vs vector va;
// segment B: NB chunks vs vb (NB==0 => single segment). Depth-1 prefetch
// keeps one chunk in flight through compute including the A->B boundary.
template <int NA, int NB>
__device__ __forceinline__ void dots_pipe(
    const __half* __restrict__ a0, const __half* __restrict__ a1,
    const __half* __restrict__ a2, const float* __restrict__ va,
    const __half* __restrict__ b0, const __half* __restrict__ b1,
    const __half* __restrict__ b2, const float* __restrict__ vb,
    char* buf, int lane,
    float& ra0, float& ra1, float& ra2,
    float& rb0, float& rb1, float& rb2)
{
    float A0 = 0.f, A1 = 0.f, A2 = 0.f, B0 = 0.f, B1 = 0.f, B2 = 0.f;
    issue_chunk(a0, a1, a2, 0, buf, 0, lane);
#pragma unroll
    for (int c = 0; c < NA + NB; ++c) {
        const int n = c + 1;
        if (n < NA + NB) {
            if (n < NA) issue_chunk(a0, a1, a2, n, buf, n & 1, lane);
            else        issue_chunk(b0, b1, b2, n - NA, buf, n & 1, lane);
            __pipeline_wait_prior(1);
        } else {
            __pipeline_wait_prior(0);
        }
        if (c < NA) compute_chunk(va, c, buf, c & 1, lane, A0, A1, A2);
        else        compute_chunk(vb, c - NA, buf, c & 1, lane, B0, B1, B2);
    }
    ra0 = warp_red(A0); ra1 = warp_red(A1); ra2 = warp_red(A2);
    if (NB > 0) { rb0 = warp_red(B0); rb1 = warp_red(B1); rb2 = warp_red(B2); }
}

__device__ __forceinline__ float sigf(float v) { return 1.f / (1.f + expf(-v)); }

// ---------------- fp32 -> fp16 weight conversion ------------------------------
__global__ void f2h_kernel(const float* __restrict__ src, __half* __restrict__ dst, int n) {
    const int stride = gridDim.x * blockDim.x * 8;
    for (int i = (blockIdx.x * blockDim.x + threadIdx.x) * 8; i < n; i += stride) {
        const float4 a = __ldg(reinterpret_cast<const float4*>(src + i));
        const float4 b = __ldg(reinterpret_cast<const float4*>(src + i + 4));
        const __half2 h0 = __floats2half2_rn(a.x, a.y);
        const __half2 h1 = __floats2half2_rn(a.z, a.w);
        const __half2 h2 = __floats2half2_rn(b.x, b.y);
        const __half2 h3 = __floats2half2_rn(b.z, b.w);
        uint4 o;
        o.x = *reinterpret_cast<const unsigned int*>(&h0);
        o.y = *reinterpret_cast<const unsigned int*>(&h1);
        o.z = *reinterpret_cast<const unsigned int*>(&h2);
        o.w = *reinterpret_cast<const unsigned int*>(&h3);
        *reinterpret_cast<uint4*>(dst + i) = o;
    }
}

// ---------------- encoder: e1 (1->2048) + e2 (2048->1024), pipelined ----------
__global__ void __launch_bounds__(NTHR, 1) gru_encoder(
    const float* __restrict__ x,
    const float* __restrict__ w1ih, const float* __restrict__ b1ih,
    const float* __restrict__ b1hh,
    const float* __restrict__ b2ih, const float* __restrict__ b2hh,
    int nblk)
{
    extern __shared__ __align__(16) float smem[];
    float* s_h1 = smem;                      // h1(t-1) == ys1(t-1)
    float* s_h2 = smem + H1;                 // h2(t-2)
    char*  wbuf = reinterpret_cast<char*>(smem + H1 + H2)
                  + (threadIdx.x >> 5) * WBUF_BYTES;
    const int tid  = threadIdx.x;
    const int lane = tid & 31;
    const int gw   = blockIdx.x * WPB + (tid >> 5);
    const long long NW = (long long)nblk * WPB;

    // R5 traffic-weighted static partition: e1 item = 2 units, e2 item = 3.
    const long long Q = 7168;
    int e1lo = (int)(((long long)gw * Q + 2 * NW - 1) / (2 * NW));
    int e1hi = (int)(((long long)(gw + 1) * Q + 2 * NW - 1) / (2 * NW));
    if (e1lo > H1) e1lo = H1;
    if (e1hi > H1) e1hi = H1;
    const long long p0 = (long long)gw * Q - 4096 * NW;
    const long long p1 = (long long)(gw + 1) * Q - 4096 * NW;
    int e2lo = p0 > 0 ? (int)((p0 + 3 * NW - 1) / (3 * NW)) : 0;
    int e2hi = p1 > 0 ? (int)((p1 + 3 * NW - 1) / (3 * NW)) : 0;
    if (e2lo > H2) e2lo = H2;
    if (e2hi > H2) e2hi = H2;

    for (int t = 0; t <= TT; ++t) {
        const float* h1p = g_h1[(t + 1) & 1];   // parity of (t-1)
        for (int i = tid * 4; i < H1; i += NTHR * 4) {
            float4 v = (t == 0) ? make_float4(0.f, 0.f, 0.f, 0.f)
                                : __ldcg(reinterpret_cast<const float4*>(h1p + i));
            *reinterpret_cast<float4*>(s_h1 + i) = v;
        }
        const float* h2p = g_h2[t & 1];          // parity of (t-2)
        for (int i = tid * 4; i < H2; i += NTHR * 4) {
            float4 v = (t <= 1) ? make_float4(0.f, 0.f, 0.f, 0.f)
                                : __ldcg(reinterpret_cast<const float4*>(h2p + i));
            *reinterpret_cast<float4*>(s_h2 + i) = v;
        }
        __syncthreads();

        if (t < TT) {
            const float xt = __ldg(x + t);
            for (int i = e1lo; i < e1hi; ++i) {
                float hr, hz, hn, u0, u1, u2;
                dots_pipe<4, 0>(c_w1hh + (size_t)i * H1,
                                c_w1hh + (size_t)(i + H1) * H1,
                                c_w1hh + (size_t)(i + 2 * H1) * H1, s_h1,
                                (const __half*)0, (const __half*)0,
                                (const __half*)0, (const float*)0,
                                wbuf, lane, hr, hz, hn, u0, u1, u2);
                if (lane == 0) {
                    const float xr = fmaf(xt, __ldg(w1ih + i),          __ldg(b1ih + i));
                    const float xz = fmaf(xt, __ldg(w1ih + i + H1),     __ldg(b1ih + i + H1));
                    const float xn = fmaf(xt, __ldg(w1ih + i + 2 * H1), __ldg(b1ih + i + 2 * H1));
                    hr += __ldg(b1hh + i);
                    hz += __ldg(b1hh + i + H1);
                    hn += __ldg(b1hh + i + 2 * H1);
                    const float r = sigf(xr + hr);
                    const float z = sigf(xz + hz);
                    const float n = tanhf(xn + r * hn);
                    g_h1[t & 1][i] = (1.f - z) * n + z * s_h1[i];
                }
            }
        }
        if (t >= 1) {
            for (int i = e2lo; i < e2hi; ++i) {     // computing h2(t-1)
                float xr, xz, xn, hr, hz, hn;
                dots_pipe<4, 2>(c_w2ih + (size_t)i * H1,
                                c_w2ih + (size_t)(i + H2) * H1,
                                c_w2ih + (size_t)(i + 2 * H2) * H1, s_h1,
                                c_w2hh + (size_t)i * H2,
                                c_w2hh + (size_t)(i + H2) * H2,
                                c_w2hh + (size_t)(i + 2 * H2) * H2, s_h2,
                                wbuf, lane, xr, xz, xn, hr, hz, hn);
                if (lane == 0) {
                    xr += __ldg(b2ih + i);
                    xz += __ldg(b2ih + i + H2);
                    xn += __ldg(b2ih + i + 2 * H2);
                    hr += __ldg(b2hh + i);
                    hz += __ldg(b2hh + i + H2);
                    hn += __ldg(b2hh + i + 2 * H2);
                    const float r = sigf(xr + hr);
                    const float z = sigf(xz + hz);
                    const float n = tanhf(xn + r * hn);
                    g_h2[(t + 1) & 1][i] = (1.f - z) * n + z * s_h2[i];
                }
            }
        }
        gridsync(nblk);
    }
}

// ---------------- d1 constant input-gate preactivation ------------------------
__global__ void gru_xgd1(const float* __restrict__ d1ih,
                         const float* __restrict__ d1bih)
{
    const int lane = threadIdx.x & 31;
    const int gw = blockIdx.x * (blockDim.x >> 5) + (threadIdx.x >> 5);
    const int nw = gridDim.x * (blockDim.x >> 5);
    for (int j = gw; j < 3 * H2; j += nw) {
        float a = 0.f;
        const float* w = d1ih + (size_t)j * H2;
#pragma unroll 4
        for (int q = 0; q < H2 / 128; ++q) {
            const int idx = q * 128 + lane * 4;
            const float4 r = __ldg(reinterpret_cast<const float4*>(w + idx));
            const float4 v = __ldcg(reinterpret_cast<const float4*>(&g_h2[1][idx]));
            a = fmaf(r.x, v.x, a); a = fmaf(r.y, v.y, a);
            a = fmaf(r.z, v.z, a); a = fmaf(r.w, v.w, a);
        }
        a = warp_red(a);
        if (lane == 0) g_xgd1[j] = a + __ldg(d1bih + j);
    }
}

// ---------------- decoder: d1 (const in ->1024) + d2 (1024->2048), pipelined --
__global__ void __launch_bounds__(NTHR, 1) gru_decoder(
    const float* __restrict__ b1hh,
    const float* __restrict__ b2ih, const float* __restrict__ b2hh,
    int nblk)
{
    extern __shared__ __align__(16) float smem[];
    float* s_d1 = smem;                      // hd1(t-1) == ys2(t-1)
    float* s_y3 = smem + H2;                 // ys3(t-2)
    char*  wbuf = reinterpret_cast<char*>(smem + H1 + H2)
                  + (threadIdx.x >> 5) * WBUF_BYTES;
    const int tid  = threadIdx.x;
    const int lane = tid & 31;
    const int gw   = blockIdx.x * WPB + (tid >> 5);
    const long long NW = (long long)nblk * WPB;

    // R5 partition: d1 item = 1 unit, d2 item = 3 units. Q = 7168.
    const long long Q = 7168;
    int d1lo = (int)(((long long)gw * Q + NW - 1) / NW);
    int d1hi = (int)(((long long)(gw + 1) * Q + NW - 1) / NW);
    if (d1lo > H2) d1lo = H2;
    if (d1hi > H2) d1hi = H2;
    const long long p0 = (long long)gw * Q - 1024 * NW;
    const long long p1 = (long long)(gw + 1) * Q - 1024 * NW;
    int d2lo = p0 > 0 ? (int)((p0 + 3 * NW - 1) / (3 * NW)) : 0;
    int d2hi = p1 > 0 ? (int)((p1 + 3 * NW - 1) / (3 * NW)) : 0;
    if (d2lo > H1) d2lo = H1;
    if (d2hi > H1) d2hi = H1;

    for (int t = 0; t <= TT; ++t) {
        const int s = t - 1;                    // d2 computes ys3[s]
        const float* d1p = g_hd1[(t + 1) & 1];
        for (int i = tid * 4; i < H2; i += NTHR * 4) {
            float4 v = (t == 0) ? make_float4(0.f, 0.f, 0.f, 0.f)
                                : __ldcg(reinterpret_cast<const float4*>(d1p + i));
            *reinterpret_cast<float4*>(s_d1 + i) = v;
        }
        for (int i = tid * 4; i < H1; i += NTHR * 4) {
            float4 v = (t <= 1) ? make_float4(0.f, 0.f, 0.f, 0.f)
                                : __ldcg(reinterpret_cast<const float4*>(&g_ys3[s - 1][i]));
            *reinterpret_cast<float4*>(s_y3 + i) = v;
        }
        __syncthreads();

        if (t < TT) {
            for (int i = d1lo; i < d1hi; ++i) {   // d1 output: hd1(t)
                float hr, hz, hn, u0, u1, u2;
                dots_pipe<2, 0>(c_d1hh + (size_t)i * H2,
                                c_d1hh + (size_t)(i + H2) * H2,
                                c_d1hh + (size_t)(i + 2 * H2) * H2, s_d1,
                                (const __half*)0, (const __half*)0,
                                (const __half*)0, (const float*)0,
                                wbuf, lane, hr, hz, hn, u0, u1, u2);
                if (lane == 0) {
                    const float xr = g_xgd1[i];             // includes bih
                    const float xz = g_xgd1[i + H2];
                    const float xn = g_xgd1[i + 2 * H2];
                    hr += __ldg(b1hh + i);
                    hz += __ldg(b1hh + i + H2);
                    hn += __ldg(b1hh + i + 2 * H2);
                    const float r = sigf(xr + hr);
                    const float z = sigf(xz + hz);
                    const float n = tanhf(xn + r * hn);
                    g_hd1[t & 1][i] = (1.f - z) * n + z * s_d1[i];
                }
            }
        }
        if (t >= 1) {
            for (int i = d2lo; i < d2hi; ++i) {   // d2 output: ys3[s]
                float xr, xz, xn, hr, hz, hn;
                dots_pipe<2, 4>(c_d2ih + (size_t)i * H2,
                                c_d2ih + (size_t)(i + H1) * H2,
                                c_d2ih + (size_t)(i + 2 * H1) * H2, s_d1,
                                c_d2hh + (size_t)i * H1,
                                c_d2hh + (size_t)(i + H1) * H1,
                                c_d2hh + (size_t)(i + 2 * H1) * H1, s_y3,
                                wbuf, lane, xr, xz, xn, hr, hz, hn);
                if (lane == 0) {
                    xr += __ldg(b2ih + i);
                    xz += __ldg(b2ih + i + H1);
                    xn += __ldg(b2ih + i + 2 * H1);
                    hr += __ldg(b2hh + i);
                    hz += __ldg(b2hh + i + H1);
                    hn += __ldg(b2hh + i + 2 * H1);
                    const float r = sigf(xr + hr);
                    const float z = sigf(xz + hz);
                    const float n = tanhf(xn + r * hn);
                    g_ys3[s][i] = (1.f - z) * n + z * s_y3[i];
                }
            }
        }
        gridsync(nblk);
    }
}

// ---------------- output head: out[t] = ys3[t] . out_W + out_b ----------------
__global__ void gru_output(const float* __restrict__ ow,
                           const float* __restrict__ ob,
                           float* __restrict__ out)
{
    const int lane = threadIdx.x & 31;
    const int gw = blockIdx.x * (blockDim.x >> 5) + (threadIdx.x >> 5);
    const int nw = gridDim.x * (blockDim.x >> 5);
    for (int t = gw; t < TT; t += nw) {
        float a = 0.f;
#pragma unroll 4
        for (int q = 0; q < H1 / 128; ++q) {
            const int idx = q * 128 + lane * 4;
            const float4 w = __ldg(reinterpret_cast<const float4*>(ow + idx));
            const float4 v = *reinterpret_cast<const float4*>(&g_ys3[t][idx]);
            a = fmaf(w.x, v.x, a); a = fmaf(w.y, v.y, a);
            a = fmaf(w.z, v.z, a); a = fmaf(w.w, v.w, a);
        }
        a = warp_red(a);
        if (lane == 0) out[t] = a + __ldg(ob);
    }
}

// ---------------- launch ------------------------------------------------------
extern "C" void kernel_launch(void* const* d_in, const int* in_sizes, int n_in,
                              void* d_out, int out_size) {
    const float* x      = (const float*)d_in[0];
    const float* e1_Wih = (const float*)d_in[1];
    const float* e1_Whh = (const float*)d_in[2];
    const float* e1_bih = (const float*)d_in[3];
    const float* e1_bhh = (const float*)d_in[4];
    const float* e2_Wih = (const float*)d_in[5];
    const float* e2_Whh = (const float*)d_in[6];
    const float* e2_bih = (const float*)d_in[7];
    const float* e2_bhh = (const float*)d_in[8];
    const float* d1_Wih = (const float*)d_in[9];
    const float* d1_Whh = (const float*)d_in[10];
    const float* d1_bih = (const float*)d_in[11];
    const float* d1_bhh = (const float*)d_in[12];
    const float* d2_Wih = (const float*)d_in[13];
    const float* d2_Whh = (const float*)d_in[14];
    const float* d2_bih = (const float*)d_in[15];
    const float* d2_bhh = (const float*)d_in[16];
    const float* out_W  = (const float*)d_in[17];
    const float* out_b  = (const float*)d_in[18];

    int nblk = 148;
    cudaDeviceGetAttribute(&nblk, cudaDevAttrMultiProcessorCount, 0);

    cudaFuncSetAttribute(gru_encoder, cudaFuncAttributeMaxDynamicSharedMemorySize, SMEM_TOTAL);
    cudaFuncSetAttribute(gru_decoder, cudaFuncAttributeMaxDynamicSharedMemorySize, SMEM_TOTAL);

    __half* p_w1hh; cudaGetSymbolAddress((void**)&p_w1hh, c_w1hh);
    __half* p_w2ih; cudaGetSymbolAddress((void**)&p_w2ih, c_w2ih);
    __half* p_w2hh; cudaGetSymbolAddress((void**)&p_w2hh, c_w2hh);
    __half* p_d1hh; cudaGetSymbolAddress((void**)&p_d1hh, c_d1hh);
    __half* p_d2ih; cudaGetSymbolAddress((void**)&p_d2ih, c_d2ih);
    __half* p_d2hh; cudaGetSymbolAddress((void**)&p_d2hh, c_d2hh);

    f2h_kernel<<<512, 256>>>(e1_Whh, p_w1hh, 3 * H1 * H1);
    f2h_kernel<<<512, 256>>>(e2_Wih, p_w2ih, 3 * H2 * H1);
    f2h_kernel<<<512, 256>>>(e2_Whh, p_w2hh, 3 * H2 * H2);
    f2h_kernel<<<512, 256>>>(d1_Whh, p_d1hh, 3 * H2 * H2);
    f2h_kernel<<<512, 256>>>(d2_Wih, p_d2ih, 3 * H1 * H2);
    f2h_kernel<<<512, 256>>>(d2_Whh, p_d2hh, 3 * H1 * H1);

    gru_encoder<<<nblk, NTHR, SMEM_TOTAL>>>(x, e1_Wih, e1_bih, e1_bhh,
                                            e2_bih, e2_bhh, nblk);
    gru_xgd1<<<96, 256>>>(d1_Wih, d1_bih);
    gru_decoder<<<nblk, NTHR, SMEM_TOTAL>>>(d1_bhh, d2_bih, d2_bhh, nblk);
    gru_output<<<256, 256>>>(out_W, out_b, (float*)d_out);
}